// round 14
// baseline (speedup 1.0000x reference)
#include <cuda_runtime.h>
#include <cuda_fp16.h>
#include <math.h>

#define BB    64
#define PP    196
#define EE    2048
#define HH    512
#define EMBD  512
#define VSZ   10000
#define TCAP  50
#define TMAXX 49
#define BPP   (BB*PP)
#define KIH   (EE+EMBD)       // 2560
#define KCAT  3072            // EE+EMBD+HH

#define PRED_SZ   ((size_t)BB*TCAP*VSZ)
#define ALPHA_OFF PRED_SZ
#define ALPHA_SZ  ((size_t)BB*TCAP*PP)
#define DEC_OFF   (ALPHA_OFF + ALPHA_SZ)

// ---------------- scratch ----------------
__device__ __half g_xwx_h[(size_t)BPP*EE];     // fp16 attention projections
__device__ __half g_feat_h[(size_t)BPP*EE];    // fp16 features
__device__ __half g_Wxh[(size_t)EE*EE];        // fp16 Wx weight
__device__ __half g_hwh_h[BB*EE];
__device__ float g_fm  [BB*EE];
__device__ float g_h   [BB*HH];
__device__ float g_gate[BB*EE];
__device__ float g_inp [BB*KCAT];
__device__ int   g_dec [BB];
__device__ float g_part[(size_t)111*8*8192];
__device__ unsigned g_cnt[128];                // zero-init; finisher resets
__device__ float g_Wcomb[4096*512];            // [Wh_w ; f_beta_w]
__device__ float g_bcomb[4096];
__device__ float g_Wg[(size_t)2048*KCAT];      // gate-interleaved GRU weight
__device__ float g_bg[2048];

// ---------------- helpers ----------------
__device__ __forceinline__ unsigned tf32c(float x){
    unsigned r; asm("cvt.rna.tf32.f32 %0, %1;" : "=r"(r) : "f"(x)); return r;
}
__device__ __forceinline__ void mma8(float* c, unsigned a0,unsigned a1,unsigned a2,unsigned a3,
                                     unsigned b0,unsigned b1){
    asm volatile("mma.sync.aligned.m16n8k8.row.col.f32.tf32.tf32.f32 "
        "{%0,%1,%2,%3}, {%4,%5,%6,%7}, {%8,%9}, {%0,%1,%2,%3};"
        : "+f"(c[0]),"+f"(c[1]),"+f"(c[2]),"+f"(c[3])
        : "r"(a0),"r"(a1),"r"(a2),"r"(a3),"r"(b0),"r"(b1));
}
__device__ __forceinline__ void mma16h(float* c, unsigned a0,unsigned a1,unsigned a2,unsigned a3,
                                       unsigned b0,unsigned b1){
    asm volatile("mma.sync.aligned.m16n8k16.row.col.f32.f16.f16.f32 "
        "{%0,%1,%2,%3}, {%4,%5,%6,%7}, {%8,%9}, {%0,%1,%2,%3};"
        : "+f"(c[0]),"+f"(c[1]),"+f"(c[2]),"+f"(c[3])
        : "r"(a0),"r"(a1),"r"(a2),"r"(a3),"r"(b0),"r"(b1));
}
__device__ __forceinline__ unsigned hadd2u(unsigned a, unsigned b){
    unsigned r; asm("add.f16x2 %0,%1,%2;" : "=r"(r) : "r"(a), "r"(b)); return r;
}
__device__ __forceinline__ unsigned tanh2(unsigned x){
    unsigned r; asm("tanh.approx.f16x2 %0,%1;" : "=r"(r) : "r"(x)); return r;
}
__device__ __forceinline__ void cpa16(void* smem, const void* g){
    unsigned sa = (unsigned)__cvta_generic_to_shared(smem);
    asm volatile("cp.async.cg.shared.global [%0], [%1], 16;" :: "r"(sa), "l"(g));
}
__device__ __forceinline__ void cpcommit(){ asm volatile("cp.async.commit_group;"); }
__device__ __forceinline__ void cpwait1(){ asm volatile("cp.async.wait_group 1;"); }
__device__ __forceinline__ float sigf(float x){ return 1.f/(1.f+expf(-x)); }
__device__ __forceinline__ float sigfast(float x){ return 1.f/(1.f+__expf(-x)); }

// ---------------- preamble ----------------
__global__ void dec_kernel(const int* __restrict__ lengths, float* __restrict__ outp){
    int b = threadIdx.x;
    if (b < BB){ int d = lengths[b]-1; g_dec[b] = d; outp[DEC_OFF+b] = (float)d; }
}

__global__ __launch_bounds__(256) void mean_kernel(const float* __restrict__ feat){
    int b = blockIdx.y;
    int e = blockIdx.x*256 + threadIdx.x;
    const float* f = feat + (size_t)b*PP*EE + e;
    float s = 0.f;
    #pragma unroll 4
    for (int p = 0; p < PP; p++) s += f[(size_t)p*EE];
    g_fm[b*EE+e] = s * (1.f/(float)PP);
}

// fp32->fp16 converters: device-symbol destinations referenced INSIDE the kernel
// (passing __device__ symbols as host launch args was the R7-R12 bug)
__global__ __launch_bounds__(256) void feat2h(const float* __restrict__ f){
    size_t i = (size_t)blockIdx.x*256 + threadIdx.x;   // over BPP*EE/2 half2
    float2 v = ((const float2*)f)[i];
    ((__half2*)g_feat_h)[i] = __floats2half2_rn(v.x, v.y);
}
__global__ __launch_bounds__(256) void wx2h(const float* __restrict__ w){
    size_t i = (size_t)blockIdx.x*256 + threadIdx.x;   // over EE*EE/2 half2
    float2 v = ((const float2*)w)[i];
    ((__half2*)g_Wxh)[i] = __floats2half2_rn(v.x, v.y);
}

__global__ __launch_bounds__(256) void build_wcomb(const float* __restrict__ Whw, const float* __restrict__ Whb,
                                                   const float* __restrict__ fbw, const float* __restrict__ fbb){
    int idx = blockIdx.x*256 + threadIdx.x;      // 4096*512
    int n = idx >> 9, k = idx & 511;
    g_Wcomb[idx] = (n < EE) ? Whw[n*HH+k] : fbw[(n-EE)*HH+k];
    if (k == 0) g_bcomb[n] = (n < EE) ? Whb[n] : fbb[n-EE];
}

// gate-interleaved GRU weight: new row m = j*4+q, q in {r,z,n,hn}
__global__ __launch_bounds__(256) void build_wg(const float* __restrict__ gihw, const float* __restrict__ gihb,
                                                const float* __restrict__ ghhw, const float* __restrict__ ghhb){
    size_t idx = (size_t)blockIdx.x*256 + threadIdx.x;    // 2048*3072
    int m = (int)(idx / KCAT), k = (int)(idx % KCAT);
    int j = m >> 2, q = m & 3;
    int n = q*512 + j;
    float v;
    if (n < 1024)       v = (k < KIH) ? gihw[(size_t)n*KIH+k] : ghhw[(size_t)n*HH + (k-KIH)];
    else if (n < 1536)  v = (k < KIH) ? gihw[(size_t)n*KIH+k] : 0.f;
    else                v = (k < KIH) ? 0.f : ghhw[(size_t)(n-512)*HH + (k-KIH)];
    g_Wg[idx] = v;
    if (k == 0){
        float bb;
        if (n < 1024)      bb = gihb[n] + ghhb[n];
        else if (n < 1536) bb = gihb[n];
        else               bb = ghhb[n-512];
        g_bg[m] = bb;
    }
}

__global__ __launch_bounds__(256) void h0_kernel(const float* __restrict__ W,
                                                 const float* __restrict__ bv){
    int gw = blockIdx.x*8 + (threadIdx.x >> 5);
    int lane = threadIdx.x & 31;
    int b = gw >> 9, n = gw & 511;
    const float* a = g_fm + (size_t)b*EE;
    const float* w = W + (size_t)n*EE;
    float s = 0.f;
    #pragma unroll 4
    for (int k = lane; k < EE; k += 32) s = fmaf(a[k], w[k], s);
    #pragma unroll
    for (int o = 16; o > 0; o >>= 1) s += __shfl_xor_sync(0xffffffffu, s, o);
    if (lane == 0) g_h[b*HH + n] = s + bv[n];
}

// ---------------- xwx: fp16 mma GEMM from device-global fp16 buffers ----------------
#define XPH 40
__global__ __launch_bounds__(256) void xwx_h16(const float* __restrict__ bias){
    __shared__ __half As[2][128*XPH];
    __shared__ __half Bs[2][128*XPH];
    int tid = threadIdx.x;
    int m0 = blockIdx.y*128, n0 = blockIdx.x*128;
    int rc = tid >> 1, kc = (tid & 1) * 16;
    const __half* Ap = g_feat_h + (size_t)(m0+rc)*EE + kc;
    const __half* Wp = g_Wxh   + (size_t)(n0+rc)*EE + kc;
    int wq = tid >> 5, lane = tid & 31, g = lane >> 2, ct = lane & 3;
    int wm = (wq >> 2) * 64, wn = (wq & 3) * 32;

    float acc[4][4][4];
    #pragma unroll
    for (int i=0;i<4;i++)
        #pragma unroll
        for (int j=0;j<4;j++)
            #pragma unroll
            for (int q=0;q<4;q++) acc[i][j][q] = 0.f;

    #pragma unroll
    for (int s = 0; s < 2; s++){
        int k0 = s*32;
        cpa16(&As[s][rc*XPH + kc],     Ap + k0);
        cpa16(&As[s][rc*XPH + kc + 8], Ap + k0 + 8);
        cpa16(&Bs[s][rc*XPH + kc],     Wp + k0);
        cpa16(&Bs[s][rc*XPH + kc + 8], Wp + k0 + 8);
        cpcommit();
    }

    for (int k0 = 0; k0 < EE; k0 += 32){
        int s = (k0 >> 5) & 1;
        cpwait1();
        __syncthreads();
        #pragma unroll
        for (int kq = 0; kq < 2; kq++){
            int k16 = kq*16;
            unsigned ah[4][4], bh[4][2];
            #pragma unroll
            for (int mt=0;mt<4;mt++){
                int rm = wm + mt*16;
                ah[mt][0] = *(const unsigned*)&As[s][(rm+g  )*XPH + k16 + 2*ct];
                ah[mt][1] = *(const unsigned*)&As[s][(rm+g+8)*XPH + k16 + 2*ct];
                ah[mt][2] = *(const unsigned*)&As[s][(rm+g  )*XPH + k16 + 2*ct + 8];
                ah[mt][3] = *(const unsigned*)&As[s][(rm+g+8)*XPH + k16 + 2*ct + 8];
            }
            #pragma unroll
            for (int nt=0;nt<4;nt++){
                int nb = wn + nt*8;
                bh[nt][0] = *(const unsigned*)&Bs[s][(nb+g)*XPH + k16 + 2*ct];
                bh[nt][1] = *(const unsigned*)&Bs[s][(nb+g)*XPH + k16 + 2*ct + 8];
            }
            #pragma unroll
            for (int mt=0;mt<4;mt++)
                #pragma unroll
                for (int nt=0;nt<4;nt++)
                    mma16h(acc[mt][nt], ah[mt][0],ah[mt][1],ah[mt][2],ah[mt][3], bh[nt][0],bh[nt][1]);
        }
        __syncthreads();
        {
            int kn = k0 + 64;
            if (kn < EE){
                cpa16(&As[s][rc*XPH + kc],     Ap + kn);
                cpa16(&As[s][rc*XPH + kc + 8], Ap + kn + 8);
                cpa16(&Bs[s][rc*XPH + kc],     Wp + kn);
                cpa16(&Bs[s][rc*XPH + kc + 8], Wp + kn + 8);
            }
            cpcommit();   // unconditional: pending-group count stays honest
        }
    }
    #pragma unroll
    for (int mt=0;mt<4;mt++)
        #pragma unroll
        for (int nt=0;nt<4;nt++){
            int cn = n0 + wn + nt*8 + 2*ct;
            float b0 = bias[cn], b1 = bias[cn+1];
            size_t r1 = (size_t)(m0 + wm + mt*16 + g);
            *(__half2*)&g_xwx_h[r1*EE + cn]     = __floats2half2_rn(acc[mt][nt][0]+b0, acc[mt][nt][1]+b1);
            *(__half2*)&g_xwx_h[(r1+8)*EE + cn] = __floats2half2_rn(acc[mt][nt][2]+b0, acc[mt][nt][3]+b1);
        }
}

// ---------------- shared 64x128 compensated-tf32 tile body ----------------
__device__ __forceinline__ void mm_body(const float* __restrict__ A, int lda,
                                        const float* __restrict__ W0, int wrows, int K,
                                        int kbeg, int kend,
                                        unsigned (*As)[64][17], unsigned (*Ws)[128][17],
                                        float acc[2][4][4]){
    int tid = threadIdx.x;
    int arow = tid >> 2, acol = (tid & 3) * 4;
    int brow = tid >> 1, bcol = (tid & 1) * 8;
    bool bok = brow < wrows;
    const float* Ap = A + (size_t)arow*lda + acol;
    const float* Wp = W0 + (size_t)brow*K + bcol;
    int w = tid >> 5, lane = tid & 31, g = lane >> 2, c = lane & 3;
    int wm = (w >> 2) * 32, wn = (w & 3) * 32;
    float4 ra = *(const float4*)(Ap + kbeg);
    float4 rb0 = make_float4(0,0,0,0), rb1 = rb0;
    if (bok){ rb0 = *(const float4*)(Wp + kbeg); rb1 = *(const float4*)(Wp + kbeg + 4); }
    for (int k0 = kbeg; k0 < kend; k0 += 16){
        float av[4] = {ra.x,ra.y,ra.z,ra.w};
        #pragma unroll
        for (int j=0;j<4;j++){
            unsigned hi = tf32c(av[j]);
            As[0][arow][acol+j] = hi;
            As[1][arow][acol+j] = tf32c(av[j] - __uint_as_float(hi));
        }
        float bvv[8] = {rb0.x,rb0.y,rb0.z,rb0.w, rb1.x,rb1.y,rb1.z,rb1.w};
        #pragma unroll
        for (int j=0;j<8;j++){
            unsigned hi = tf32c(bvv[j]);
            Ws[0][brow][bcol+j] = hi;
            Ws[1][brow][bcol+j] = tf32c(bvv[j] - __uint_as_float(hi));
        }
        __syncthreads();
        if (k0 + 16 < kend){
            ra = *(const float4*)(Ap + k0 + 16);
            if (bok){ rb0 = *(const float4*)(Wp + k0 + 16); rb1 = *(const float4*)(Wp + k0 + 20); }
        }
        #pragma unroll
        for (int kq = 0; kq < 2; kq++){
            int k8 = kq*8;
            unsigned ah[2][4], al[2][4], bh[4][2], bl[4][2];
            #pragma unroll
            for (int mt=0;mt<2;mt++){
                int rm = wm + mt*16;
                ah[mt][0]=As[0][rm+g][k8+c];   ah[mt][1]=As[0][rm+g+8][k8+c];
                ah[mt][2]=As[0][rm+g][k8+c+4]; ah[mt][3]=As[0][rm+g+8][k8+c+4];
                al[mt][0]=As[1][rm+g][k8+c];   al[mt][1]=As[1][rm+g+8][k8+c];
                al[mt][2]=As[1][rm+g][k8+c+4]; al[mt][3]=As[1][rm+g+8][k8+c+4];
            }
            #pragma unroll
            for (int nt=0;nt<4;nt++){
                int nb = wn + nt*8;
                bh[nt][0]=Ws[0][nb+g][k8+c]; bh[nt][1]=Ws[0][nb+g][k8+c+4];
                bl[nt][0]=Ws[1][nb+g][k8+c]; bl[nt][1]=Ws[1][nb+g][k8+c+4];
            }
            #pragma unroll
            for (int mt=0;mt<2;mt++)
                #pragma unroll
                for (int nt=0;nt<4;nt++){
                    mma8(acc[mt][nt], ah[mt][0],ah[mt][1],ah[mt][2],ah[mt][3], bh[nt][0],bh[nt][1]);
                    mma8(acc[mt][nt], al[mt][0],al[mt][1],al[mt][2],al[mt][3], bh[nt][0],bh[nt][1]);
                    mma8(acc[mt][nt], ah[mt][0],ah[mt][1],ah[mt][2],ah[mt][3], bl[nt][0],bl[nt][1]);
                }
        }
        __syncthreads();
    }
}

__device__ bool splitk_reduce(float acc[2][4][4], int slot, int ksplit){
    __shared__ unsigned s_last;
    int tid = threadIdx.x;
    int w = tid >> 5, lane = tid & 31, g = lane >> 2, c = lane & 3;
    int wm = (w >> 2) * 32, wn = (w & 3) * 32;
    float* pp = &g_part[((size_t)slot*8 + blockIdx.z)*8192];
    #pragma unroll
    for (int mt=0;mt<2;mt++)
        #pragma unroll
        for (int nt=0;nt<4;nt++){
            int r1 = wm + mt*16 + g;
            int cc = wn + nt*8 + 2*c;
            pp[r1*128 + cc]       = acc[mt][nt][0];
            pp[r1*128 + cc+1]     = acc[mt][nt][1];
            pp[(r1+8)*128 + cc]   = acc[mt][nt][2];
            pp[(r1+8)*128 + cc+1] = acc[mt][nt][3];
        }
    __threadfence();
    __syncthreads();
    if (tid == 0)
        s_last = (atomicAdd(&g_cnt[slot], 1u) == (unsigned)(ksplit-1)) ? 1u : 0u;
    __syncthreads();
    if (!s_last) return false;
    __threadfence();
    #pragma unroll
    for (int mt=0;mt<2;mt++)
        #pragma unroll
        for (int nt=0;nt<4;nt++){
            int r1 = wm + mt*16 + g;
            int cc = wn + nt*8 + 2*c;
            float s0=0.f,s1=0.f,s2=0.f,s3=0.f;
            for (int kz = 0; kz < ksplit; kz++){
                const float* q = &g_part[((size_t)slot*8 + kz)*8192];
                s0 += q[r1*128 + cc];     s1 += q[r1*128 + cc+1];
                s2 += q[(r1+8)*128 + cc]; s3 += q[(r1+8)*128 + cc+1];
            }
            acc[mt][nt][0]=s0; acc[mt][nt][1]=s1; acc[mt][nt][2]=s2; acc[mt][nt][3]=s3;
        }
    __syncthreads();
    if (tid == 0) g_cnt[slot] = 0;
    return true;
}

// ---------------- wstep: hwh/gate(t) + fc1(t-1), split-K 4 ----------------
__global__ __launch_bounds__(256) void wstep(const float* __restrict__ fc1w,
                                             const float* __restrict__ fc1b,
                                             float* __restrict__ outp, int t){
    int tile = blockIdx.x;              // 0..110
    bool isC = tile < 32;
    if (isC  && t == TMAXX) return;
    if (!isC && t == 0)     return;
    __shared__ unsigned As[2][64][17];
    __shared__ unsigned Ws[2][128][17];
    int n0 = isC ? tile*128 : (tile-32)*128;
    const float* W = isC ? (g_Wcomb + (size_t)n0*HH) : (fc1w + (size_t)n0*HH);
    int wrows = isC ? 128 : (VSZ - n0 < 128 ? VSZ - n0 : 128);
    float acc[2][4][4];
    #pragma unroll
    for (int i=0;i<2;i++)
        #pragma unroll
        for (int j=0;j<4;j++)
            #pragma unroll
            for (int q=0;q<4;q++) acc[i][j][q]=0.f;
    int kb = blockIdx.z * (HH/4);
    mm_body(g_h, HH, W, wrows, HH, kb, kb + HH/4, As, Ws, acc);
    if (!splitk_reduce(acc, tile, 4)) return;

    int tid = threadIdx.x;
    int w = tid >> 5, lane = tid & 31, g = lane >> 2, c = lane & 3;
    int wm = (w >> 2) * 32, wn = (w & 3) * 32;
    int tt = t - 1;
    #pragma unroll
    for (int mt=0;mt<2;mt++)
        #pragma unroll
        for (int nt=0;nt<4;nt++)
            #pragma unroll
            for (int q=0;q<4;q++){
                int r = wm + mt*16 + g + ((q>=2)?8:0);
                int n = n0 + wn + nt*8 + 2*c + (q&1);
                if (isC){
                    float v = acc[mt][nt][q] + g_bcomb[n];
                    if (n < EE) g_hwh_h[(size_t)r*EE + n] = __float2half(v);
                    else        g_gate[(size_t)r*EE + (n-EE)] = sigfast(v);
                } else {
                    if (n < VSZ && g_dec[r] >= tt)
                        outp[(size_t)r*TCAP*VSZ + (size_t)tt*VSZ + n] = acc[mt][nt][q] + fc1b[n];
                }
            }
}

// ---------------- gstep: GRU GEMM + fused combine, split-K 8 ----------------
__global__ __launch_bounds__(256) void gstep(int t){
    __shared__ __align__(16) unsigned sb[8192];
    unsigned (*As)[64][17]  = (unsigned(*)[64][17])sb;
    unsigned (*Ws)[128][17] = (unsigned(*)[128][17])(sb + 2*64*17);
    int tile = blockIdx.x;              // 0..15
    int n0 = tile*128;
    float acc[2][4][4];
    #pragma unroll
    for (int i=0;i<2;i++)
        #pragma unroll
        for (int j=0;j<4;j++)
            #pragma unroll
            for (int q=0;q<4;q++) acc[i][j][q]=0.f;
    int kb = blockIdx.z * (KCAT/8);
    mm_body(g_inp, KCAT, g_Wg + (size_t)n0*KCAT, 128, KCAT, kb, kb + KCAT/8, As, Ws, acc);
    if (!splitk_reduce(acc, tile, 8)) return;

    int tid = threadIdx.x;
    int w = tid >> 5, lane = tid & 31, g = lane >> 2, c = lane & 3;
    int wm = (w >> 2) * 32, wn = (w & 3) * 32;
    float* Gt = (float*)sb;
    #pragma unroll
    for (int mt=0;mt<2;mt++)
        #pragma unroll
        for (int nt=0;nt<4;nt++)
            #pragma unroll
            for (int q=0;q<4;q++){
                int r  = wm + mt*16 + g + ((q>=2)?8:0);
                int cc = wn + nt*8 + 2*c + (q&1);
                Gt[r*128 + cc] = acc[mt][nt][q] + g_bg[n0 + cc];
            }
    __syncthreads();
    int jbase = n0 >> 2;
    for (int idx = tid; idx < 2048; idx += 256){
        int r  = idx >> 5;
        int jl = idx & 31;
        float G0 = Gt[r*128 + jl*4 + 0];
        float G1 = Gt[r*128 + jl*4 + 1];
        float G2 = Gt[r*128 + jl*4 + 2];
        float G3 = Gt[r*128 + jl*4 + 3];
        float rr = sigf(G0), zz = sigf(G1);
        float nn = tanhf(G2 + rr*G3);
        int j = jbase + jl;
        float h = g_h[r*HH + j];
        if (g_dec[r] >= t) g_h[r*HH + j] = (1.f - zz)*nn + zz*h;
    }
}

// ---------------- attz: attention + softmax + z + embed + h concat (1 block/batch) ----------------
__global__ __launch_bounds__(512) void attz(const float* __restrict__ Vw,
                                            const float* __restrict__ Vb,
                                            const int* __restrict__ caps,
                                            const float* __restrict__ embw,
                                            float* __restrict__ outp, int t){
    int b = blockIdx.x, tid = threadIdx.x;
    int wid = tid >> 5, lane = tid & 31;
    __shared__ unsigned shh[1024];
    __shared__ float svw[2048];
    __shared__ float slam[PP];
    __shared__ float salpha[PP];
    __shared__ float red[512];

    for (int i = tid; i < 1024; i += 512) shh[i] = ((const unsigned*)(g_hwh_h + (size_t)b*EE))[i];
    for (int i = tid; i < 2048; i += 512) svw[i] = Vw[i];
    float vb0 = Vb[0];
    __syncthreads();

    for (int p = wid; p < PP; p += 16){
        const unsigned* xr = (const unsigned*)(g_xwx_h + (size_t)(b*PP + p)*EE);
        float s = 0.f;
        #pragma unroll 4
        for (int i = lane; i < 1024; i += 32){
            unsigned tv = tanh2(hadd2u(xr[i], shh[i]));
            float2 f = __half22float2(*(__half2*)&tv);
            s = fmaf(f.x, svw[2*i], s);
            s = fmaf(f.y, svw[2*i+1], s);
        }
        #pragma unroll
        for (int o = 16; o > 0; o >>= 1) s += __shfl_xor_sync(0xffffffffu, s, o);
        if (lane == 0) slam[p] = s + vb0;
    }
    __syncthreads();

    float v = (tid < PP) ? slam[tid] : -1e30f;
    red[tid] = v; __syncthreads();
    for (int s2 = 256; s2 > 0; s2 >>= 1){ if (tid < s2) red[tid] = fmaxf(red[tid], red[tid+s2]); __syncthreads(); }
    float mx = red[0]; __syncthreads();
    float e = (tid < PP) ? expf(v - mx) : 0.f;
    red[tid] = e; __syncthreads();
    for (int s2 = 256; s2 > 0; s2 >>= 1){ if (tid < s2) red[tid] += red[tid+s2]; __syncthreads(); }
    float inv = 1.f / red[0];
    if (tid < PP) salpha[tid] = e * inv;
    __syncthreads();
    if (tid < PP && g_dec[b] >= t)
        outp[ALPHA_OFF + (size_t)b*TCAP*PP + (size_t)t*PP + tid] = salpha[tid];

    {
        const __half2* fb = (const __half2*)(g_feat_h + (size_t)b*PP*EE);
        float2 A0 = make_float2(0.f,0.f), A1 = make_float2(0.f,0.f);
        #pragma unroll 2
        for (int p = 0; p < PP; p++){
            float al = salpha[p];
            float2 f0 = __half22float2(fb[(size_t)p*1024 + tid]);
            float2 f1 = __half22float2(fb[(size_t)p*1024 + tid + 512]);
            A0.x = fmaf(al, f0.x, A0.x); A0.y = fmaf(al, f0.y, A0.y);
            A1.x = fmaf(al, f1.x, A1.x); A1.y = fmaf(al, f1.y, A1.y);
        }
        int e0 = 2*tid, e1 = 2*(tid+512);
        g_inp[(size_t)b*KCAT + e0]     = g_gate[b*EE + e0]     * A0.x;
        g_inp[(size_t)b*KCAT + e0 + 1] = g_gate[b*EE + e0 + 1] * A0.y;
        g_inp[(size_t)b*KCAT + e1]     = g_gate[b*EE + e1]     * A1.x;
        g_inp[(size_t)b*KCAT + e1 + 1] = g_gate[b*EE + e1 + 1] * A1.y;
    }

    int tok = caps[b*TCAP + t];
    g_inp[(size_t)b*KCAT + 2048 + tid] = embw[(size_t)tok*EMBD + tid];
    g_inp[(size_t)b*KCAT + 2560 + tid] = g_h[b*HH + tid];
}

// ---------------- launch ----------------
extern "C" void kernel_launch(void* const* d_in, const int* in_sizes, int n_in,
                              void* d_out, int out_size){
    const float* features = (const float*)d_in[0];
    const int*   captions = (const int*)  d_in[1];
    const int*   lengths  = (const int*)  d_in[2];
    const float* Wx_w  = (const float*)d_in[3];
    const float* Wx_b  = (const float*)d_in[4];
    const float* Wh_w  = (const float*)d_in[5];
    const float* Wh_b  = (const float*)d_in[6];
    const float* V_w   = (const float*)d_in[7];
    const float* V_b   = (const float*)d_in[8];
    const float* ih_w  = (const float*)d_in[9];
    const float* ih_b  = (const float*)d_in[10];
    const float* fb_w  = (const float*)d_in[11];
    const float* fb_b  = (const float*)d_in[12];
    const float* emb_w = (const float*)d_in[13];
    const float* gih_w = (const float*)d_in[14];
    const float* gih_b = (const float*)d_in[15];
    const float* ghh_w = (const float*)d_in[16];
    const float* ghh_b = (const float*)d_in[17];
    const float* fc1_w = (const float*)d_in[18];
    const float* fc1_b = (const float*)d_in[19];
    float* out = (float*)d_out;

    cudaMemsetAsync(d_out, 0, (size_t)out_size * sizeof(float), 0);
    dec_kernel<<<1, 64>>>(lengths, out);
    mean_kernel<<<dim3(EE/256, BB), 256>>>(features);
    feat2h<<<(int)(((size_t)BPP*EE/2)/256), 256>>>(features);
    wx2h<<<(int)(((size_t)EE*EE/2)/256), 256>>>(Wx_w);
    build_wcomb<<<(4096*512)/256, 256>>>(Wh_w, Wh_b, fb_w, fb_b);
    build_wg<<<(int)(((size_t)2048*KCAT)/256), 256>>>(gih_w, gih_b, ghh_w, ghh_b);
    h0_kernel<<<4096, 256>>>(ih_w, ih_b);
    xwx_h16<<<dim3(EE/128, BPP/128), 256>>>(Wx_b);

    for (int t = 0; t < TMAXX; t++){
        wstep<<<dim3(111, 1, 4), 256>>>(fc1_w, fc1_b, out, t);   // hwh/gate(t) + fc1(t-1)
        attz<<<BB, 512>>>(V_w, V_b, captions, emb_w, out, t);     // att + softmax + z + inp
        gstep<<<dim3(16, 1, 8), 256>>>(t);                        // GRU GEMM + combine + h update
    }
    wstep<<<dim3(111, 1, 4), 256>>>(fc1_w, fc1_b, out, TMAXX);    // final fc1(48)
}

// round 16
// speedup vs baseline: 1.5233x; 1.5233x over previous
#include <cuda_runtime.h>
#include <cuda_fp16.h>
#include <math.h>

#define BB    64
#define PP    196
#define EE    2048
#define HH    512
#define EMBD  512
#define VSZ   10000
#define TCAP  50
#define TMAXX 49
#define BPP   (BB*PP)
#define KIH   (EE+EMBD)       // 2560
#define KCAT  3072            // EE+EMBD+HH

#define PRED_SZ   ((size_t)BB*TCAP*VSZ)
#define ALPHA_OFF PRED_SZ
#define ALPHA_SZ  ((size_t)BB*TCAP*PP)
#define DEC_OFF   (ALPHA_OFF + ALPHA_SZ)

// ---------------- scratch ----------------
__device__ __half g_xwx_h[(size_t)BPP*EE];     // fp16 attention projections
__device__ __half g_feat_h[(size_t)BPP*EE];    // fp16 features
__device__ __half g_Wxh[(size_t)EE*EE];        // fp16 Wx weight
__device__ __half g_hwh_h[BB*EE];
__device__ float g_fm  [BB*EE];
__device__ float g_h   [BB*HH];
__device__ float g_gate[BB*EE];
__device__ float g_lam [BB*PP];
__device__ float g_inp [BB*KCAT];
__device__ int   g_dec [BB];
__device__ float g_part[(size_t)111*8*8192];
__device__ unsigned g_cnt[128];                // zero-init; finisher resets
__device__ float g_Wcomb[4096*512];            // [Wh_w ; f_beta_w]
__device__ float g_bcomb[4096];
__device__ float g_Wg[(size_t)2048*KCAT];      // gate-interleaved GRU weight
__device__ float g_bg[2048];

// ---------------- helpers ----------------
__device__ __forceinline__ unsigned tf32c(float x){
    unsigned r; asm("cvt.rna.tf32.f32 %0, %1;" : "=r"(r) : "f"(x)); return r;
}
__device__ __forceinline__ void mma8(float* c, unsigned a0,unsigned a1,unsigned a2,unsigned a3,
                                     unsigned b0,unsigned b1){
    asm volatile("mma.sync.aligned.m16n8k8.row.col.f32.tf32.tf32.f32 "
        "{%0,%1,%2,%3}, {%4,%5,%6,%7}, {%8,%9}, {%0,%1,%2,%3};"
        : "+f"(c[0]),"+f"(c[1]),"+f"(c[2]),"+f"(c[3])
        : "r"(a0),"r"(a1),"r"(a2),"r"(a3),"r"(b0),"r"(b1));
}
__device__ __forceinline__ void mma16h(float* c, unsigned a0,unsigned a1,unsigned a2,unsigned a3,
                                       unsigned b0,unsigned b1){
    asm volatile("mma.sync.aligned.m16n8k16.row.col.f32.f16.f16.f32 "
        "{%0,%1,%2,%3}, {%4,%5,%6,%7}, {%8,%9}, {%0,%1,%2,%3};"
        : "+f"(c[0]),"+f"(c[1]),"+f"(c[2]),"+f"(c[3])
        : "r"(a0),"r"(a1),"r"(a2),"r"(a3),"r"(b0),"r"(b1));
}
__device__ __forceinline__ unsigned hadd2u(unsigned a, unsigned b){
    unsigned r; asm("add.f16x2 %0,%1,%2;" : "=r"(r) : "r"(a), "r"(b)); return r;
}
__device__ __forceinline__ unsigned tanh2(unsigned x){
    unsigned r; asm("tanh.approx.f16x2 %0,%1;" : "=r"(r) : "r"(x)); return r;
}
__device__ __forceinline__ void cpa16(void* smem, const void* g){
    unsigned sa = (unsigned)__cvta_generic_to_shared(smem);
    asm volatile("cp.async.cg.shared.global [%0], [%1], 16;" :: "r"(sa), "l"(g));
}
__device__ __forceinline__ void cpcommit(){ asm volatile("cp.async.commit_group;"); }
__device__ __forceinline__ void cpwait1(){ asm volatile("cp.async.wait_group 1;"); }
__device__ __forceinline__ float sigf(float x){ return 1.f/(1.f+expf(-x)); }
__device__ __forceinline__ float sigfast(float x){ return 1.f/(1.f+__expf(-x)); }

// ---------------- preamble ----------------
__global__ void dec_kernel(const int* __restrict__ lengths, float* __restrict__ outp){
    int b = threadIdx.x;
    if (b < BB){ int d = lengths[b]-1; g_dec[b] = d; outp[DEC_OFF+b] = (float)d; }
}

__global__ __launch_bounds__(256) void mean_kernel(const float* __restrict__ feat){
    int b = blockIdx.y;
    int e = blockIdx.x*256 + threadIdx.x;
    const float* f = feat + (size_t)b*PP*EE + e;
    float s = 0.f;
    #pragma unroll 4
    for (int p = 0; p < PP; p++) s += f[(size_t)p*EE];
    g_fm[b*EE+e] = s * (1.f/(float)PP);
}

// fp32->fp16 converters: device-symbol destinations referenced INSIDE the kernel
__global__ __launch_bounds__(256) void feat2h(const float* __restrict__ f){
    size_t i = (size_t)blockIdx.x*256 + threadIdx.x;   // over BPP*EE/2 half2
    float2 v = ((const float2*)f)[i];
    ((__half2*)g_feat_h)[i] = __floats2half2_rn(v.x, v.y);
}
__global__ __launch_bounds__(256) void wx2h(const float* __restrict__ w){
    size_t i = (size_t)blockIdx.x*256 + threadIdx.x;   // over EE*EE/2 half2
    float2 v = ((const float2*)w)[i];
    ((__half2*)g_Wxh)[i] = __floats2half2_rn(v.x, v.y);
}

__global__ __launch_bounds__(256) void build_wcomb(const float* __restrict__ Whw, const float* __restrict__ Whb,
                                                   const float* __restrict__ fbw, const float* __restrict__ fbb){
    int idx = blockIdx.x*256 + threadIdx.x;      // 4096*512
    int n = idx >> 9, k = idx & 511;
    g_Wcomb[idx] = (n < EE) ? Whw[n*HH+k] : fbw[(n-EE)*HH+k];
    if (k == 0) g_bcomb[n] = (n < EE) ? Whb[n] : fbb[n-EE];
}

// gate-interleaved GRU weight: new row m = j*4+q, q in {r,z,n,hn}
__global__ __launch_bounds__(256) void build_wg(const float* __restrict__ gihw, const float* __restrict__ gihb,
                                                const float* __restrict__ ghhw, const float* __restrict__ ghhb){
    size_t idx = (size_t)blockIdx.x*256 + threadIdx.x;    // 2048*3072
    int m = (int)(idx / KCAT), k = (int)(idx % KCAT);
    int j = m >> 2, q = m & 3;
    int n = q*512 + j;
    float v;
    if (n < 1024)       v = (k < KIH) ? gihw[(size_t)n*KIH+k] : ghhw[(size_t)n*HH + (k-KIH)];
    else if (n < 1536)  v = (k < KIH) ? gihw[(size_t)n*KIH+k] : 0.f;
    else                v = (k < KIH) ? 0.f : ghhw[(size_t)(n-512)*HH + (k-KIH)];
    g_Wg[idx] = v;
    if (k == 0){
        float bb;
        if (n < 1024)      bb = gihb[n] + ghhb[n];
        else if (n < 1536) bb = gihb[n];
        else               bb = ghhb[n-512];
        g_bg[m] = bb;
    }
}

__global__ __launch_bounds__(256) void h0_kernel(const float* __restrict__ W,
                                                 const float* __restrict__ bv){
    int gw = blockIdx.x*8 + (threadIdx.x >> 5);
    int lane = threadIdx.x & 31;
    int b = gw >> 9, n = gw & 511;
    const float* a = g_fm + (size_t)b*EE;
    const float* w = W + (size_t)n*EE;
    float s = 0.f;
    #pragma unroll 4
    for (int k = lane; k < EE; k += 32) s = fmaf(a[k], w[k], s);
    #pragma unroll
    for (int o = 16; o > 0; o >>= 1) s += __shfl_xor_sync(0xffffffffu, s, o);
    if (lane == 0) g_h[b*HH + n] = s + bv[n];
}

// ---------------- xwx: fp16 mma GEMM from device-global fp16 buffers ----------------
#define XPH 40
__global__ __launch_bounds__(256) void xwx_h16(const float* __restrict__ bias){
    __shared__ __half As[2][128*XPH];
    __shared__ __half Bs[2][128*XPH];
    int tid = threadIdx.x;
    int m0 = blockIdx.y*128, n0 = blockIdx.x*128;
    int rc = tid >> 1, kc = (tid & 1) * 16;
    const __half* Ap = g_feat_h + (size_t)(m0+rc)*EE + kc;
    const __half* Wp = g_Wxh   + (size_t)(n0+rc)*EE + kc;
    int wq = tid >> 5, lane = tid & 31, g = lane >> 2, ct = lane & 3;
    int wm = (wq >> 2) * 64, wn = (wq & 3) * 32;

    float acc[4][4][4];
    #pragma unroll
    for (int i=0;i<4;i++)
        #pragma unroll
        for (int j=0;j<4;j++)
            #pragma unroll
            for (int q=0;q<4;q++) acc[i][j][q] = 0.f;

    #pragma unroll
    for (int s = 0; s < 2; s++){
        int k0 = s*32;
        cpa16(&As[s][rc*XPH + kc],     Ap + k0);
        cpa16(&As[s][rc*XPH + kc + 8], Ap + k0 + 8);
        cpa16(&Bs[s][rc*XPH + kc],     Wp + k0);
        cpa16(&Bs[s][rc*XPH + kc + 8], Wp + k0 + 8);
        cpcommit();
    }

    for (int k0 = 0; k0 < EE; k0 += 32){
        int s = (k0 >> 5) & 1;
        cpwait1();
        __syncthreads();
        #pragma unroll
        for (int kq = 0; kq < 2; kq++){
            int k16 = kq*16;
            unsigned ah[4][4], bh[4][2];
            #pragma unroll
            for (int mt=0;mt<4;mt++){
                int rm = wm + mt*16;
                ah[mt][0] = *(const unsigned*)&As[s][(rm+g  )*XPH + k16 + 2*ct];
                ah[mt][1] = *(const unsigned*)&As[s][(rm+g+8)*XPH + k16 + 2*ct];
                ah[mt][2] = *(const unsigned*)&As[s][(rm+g  )*XPH + k16 + 2*ct + 8];
                ah[mt][3] = *(const unsigned*)&As[s][(rm+g+8)*XPH + k16 + 2*ct + 8];
            }
            #pragma unroll
            for (int nt=0;nt<4;nt++){
                int nb = wn + nt*8;
                bh[nt][0] = *(const unsigned*)&Bs[s][(nb+g)*XPH + k16 + 2*ct];
                bh[nt][1] = *(const unsigned*)&Bs[s][(nb+g)*XPH + k16 + 2*ct + 8];
            }
            #pragma unroll
            for (int mt=0;mt<4;mt++)
                #pragma unroll
                for (int nt=0;nt<4;nt++)
                    mma16h(acc[mt][nt], ah[mt][0],ah[mt][1],ah[mt][2],ah[mt][3], bh[nt][0],bh[nt][1]);
        }
        __syncthreads();
        {
            int kn = k0 + 64;
            if (kn < EE){
                cpa16(&As[s][rc*XPH + kc],     Ap + kn);
                cpa16(&As[s][rc*XPH + kc + 8], Ap + kn + 8);
                cpa16(&Bs[s][rc*XPH + kc],     Wp + kn);
                cpa16(&Bs[s][rc*XPH + kc + 8], Wp + kn + 8);
            }
            cpcommit();   // unconditional: pending-group count stays honest
        }
    }
    #pragma unroll
    for (int mt=0;mt<4;mt++)
        #pragma unroll
        for (int nt=0;nt<4;nt++){
            int cn = n0 + wn + nt*8 + 2*ct;
            float b0 = bias[cn], b1 = bias[cn+1];
            size_t r1 = (size_t)(m0 + wm + mt*16 + g);
            *(__half2*)&g_xwx_h[r1*EE + cn]     = __floats2half2_rn(acc[mt][nt][0]+b0, acc[mt][nt][1]+b1);
            *(__half2*)&g_xwx_h[(r1+8)*EE + cn] = __floats2half2_rn(acc[mt][nt][2]+b0, acc[mt][nt][3]+b1);
        }
}

// ---------------- shared 64x128 compensated-tf32 tile body ----------------
__device__ __forceinline__ void mm_body(const float* __restrict__ A, int lda,
                                        const float* __restrict__ W0, int wrows, int K,
                                        int kbeg, int kend,
                                        unsigned (*As)[64][17], unsigned (*Ws)[128][17],
                                        float acc[2][4][4]){
    int tid = threadIdx.x;
    int arow = tid >> 2, acol = (tid & 3) * 4;
    int brow = tid >> 1, bcol = (tid & 1) * 8;
    bool bok = brow < wrows;
    const float* Ap = A + (size_t)arow*lda + acol;
    const float* Wp = W0 + (size_t)brow*K + bcol;
    int w = tid >> 5, lane = tid & 31, g = lane >> 2, c = lane & 3;
    int wm = (w >> 2) * 32, wn = (w & 3) * 32;
    float4 ra = *(const float4*)(Ap + kbeg);
    float4 rb0 = make_float4(0,0,0,0), rb1 = rb0;
    if (bok){ rb0 = *(const float4*)(Wp + kbeg); rb1 = *(const float4*)(Wp + kbeg + 4); }
    for (int k0 = kbeg; k0 < kend; k0 += 16){
        float av[4] = {ra.x,ra.y,ra.z,ra.w};
        #pragma unroll
        for (int j=0;j<4;j++){
            unsigned hi = tf32c(av[j]);
            As[0][arow][acol+j] = hi;
            As[1][arow][acol+j] = tf32c(av[j] - __uint_as_float(hi));
        }
        float bvv[8] = {rb0.x,rb0.y,rb0.z,rb0.w, rb1.x,rb1.y,rb1.z,rb1.w};
        #pragma unroll
        for (int j=0;j<8;j++){
            unsigned hi = tf32c(bvv[j]);
            Ws[0][brow][bcol+j] = hi;
            Ws[1][brow][bcol+j] = tf32c(bvv[j] - __uint_as_float(hi));
        }
        __syncthreads();
        if (k0 + 16 < kend){
            ra = *(const float4*)(Ap + k0 + 16);
            if (bok){ rb0 = *(const float4*)(Wp + k0 + 16); rb1 = *(const float4*)(Wp + k0 + 20); }
        }
        #pragma unroll
        for (int kq = 0; kq < 2; kq++){
            int k8 = kq*8;
            unsigned ah[2][4], al[2][4], bh[4][2], bl[4][2];
            #pragma unroll
            for (int mt=0;mt<2;mt++){
                int rm = wm + mt*16;
                ah[mt][0]=As[0][rm+g][k8+c];   ah[mt][1]=As[0][rm+g+8][k8+c];
                ah[mt][2]=As[0][rm+g][k8+c+4]; ah[mt][3]=As[0][rm+g+8][k8+c+4];
                al[mt][0]=As[1][rm+g][k8+c];   al[mt][1]=As[1][rm+g+8][k8+c];
                al[mt][2]=As[1][rm+g][k8+c+4]; al[mt][3]=As[1][rm+g+8][k8+c+4];
            }
            #pragma unroll
            for (int nt=0;nt<4;nt++){
                int nb = wn + nt*8;
                bh[nt][0]=Ws[0][nb+g][k8+c]; bh[nt][1]=Ws[0][nb+g][k8+c+4];
                bl[nt][0]=Ws[1][nb+g][k8+c]; bl[nt][1]=Ws[1][nb+g][k8+c+4];
            }
            #pragma unroll
            for (int mt=0;mt<2;mt++)
                #pragma unroll
                for (int nt=0;nt<4;nt++){
                    mma8(acc[mt][nt], ah[mt][0],ah[mt][1],ah[mt][2],ah[mt][3], bh[nt][0],bh[nt][1]);
                    mma8(acc[mt][nt], al[mt][0],al[mt][1],al[mt][2],al[mt][3], bh[nt][0],bh[nt][1]);
                    mma8(acc[mt][nt], ah[mt][0],ah[mt][1],ah[mt][2],ah[mt][3], bl[nt][0],bl[nt][1]);
                }
        }
        __syncthreads();
    }
}

__device__ bool splitk_reduce(float acc[2][4][4], int slot, int ksplit){
    __shared__ unsigned s_last;
    int tid = threadIdx.x;
    int w = tid >> 5, lane = tid & 31, g = lane >> 2, c = lane & 3;
    int wm = (w >> 2) * 32, wn = (w & 3) * 32;
    float* pp = &g_part[((size_t)slot*8 + blockIdx.z)*8192];
    #pragma unroll
    for (int mt=0;mt<2;mt++)
        #pragma unroll
        for (int nt=0;nt<4;nt++){
            int r1 = wm + mt*16 + g;
            int cc = wn + nt*8 + 2*c;
            pp[r1*128 + cc]       = acc[mt][nt][0];
            pp[r1*128 + cc+1]     = acc[mt][nt][1];
            pp[(r1+8)*128 + cc]   = acc[mt][nt][2];
            pp[(r1+8)*128 + cc+1] = acc[mt][nt][3];
        }
    __threadfence();
    __syncthreads();
    if (tid == 0)
        s_last = (atomicAdd(&g_cnt[slot], 1u) == (unsigned)(ksplit-1)) ? 1u : 0u;
    __syncthreads();
    if (!s_last) return false;
    __threadfence();
    #pragma unroll
    for (int mt=0;mt<2;mt++)
        #pragma unroll
        for (int nt=0;nt<4;nt++){
            int r1 = wm + mt*16 + g;
            int cc = wn + nt*8 + 2*c;
            float s0=0.f,s1=0.f,s2=0.f,s3=0.f;
            for (int kz = 0; kz < ksplit; kz++){
                const float* q = &g_part[((size_t)slot*8 + kz)*8192];
                s0 += q[r1*128 + cc];     s1 += q[r1*128 + cc+1];
                s2 += q[(r1+8)*128 + cc]; s3 += q[(r1+8)*128 + cc+1];
            }
            acc[mt][nt][0]=s0; acc[mt][nt][1]=s1; acc[mt][nt][2]=s2; acc[mt][nt][3]=s3;
        }
    __syncthreads();
    if (tid == 0) g_cnt[slot] = 0;
    return true;
}

// ---------------- wstep: hwh/gate(t) + fc1(t-1), split-K 4 ----------------
__global__ __launch_bounds__(256) void wstep(const float* __restrict__ fc1w,
                                             const float* __restrict__ fc1b,
                                             float* __restrict__ outp, int t){
    int tile = blockIdx.x;              // 0..110
    bool isC = tile < 32;
    if (isC  && t == TMAXX) return;
    if (!isC && t == 0)     return;
    __shared__ unsigned As[2][64][17];
    __shared__ unsigned Ws[2][128][17];
    int n0 = isC ? tile*128 : (tile-32)*128;
    const float* W = isC ? (g_Wcomb + (size_t)n0*HH) : (fc1w + (size_t)n0*HH);
    int wrows = isC ? 128 : (VSZ - n0 < 128 ? VSZ - n0 : 128);
    float acc[2][4][4];
    #pragma unroll
    for (int i=0;i<2;i++)
        #pragma unroll
        for (int j=0;j<4;j++)
            #pragma unroll
            for (int q=0;q<4;q++) acc[i][j][q]=0.f;
    int kb = blockIdx.z * (HH/4);
    mm_body(g_h, HH, W, wrows, HH, kb, kb + HH/4, As, Ws, acc);
    if (!splitk_reduce(acc, tile, 4)) return;

    int tid = threadIdx.x;
    int w = tid >> 5, lane = tid & 31, g = lane >> 2, c = lane & 3;
    int wm = (w >> 2) * 32, wn = (w & 3) * 32;
    int tt = t - 1;
    #pragma unroll
    for (int mt=0;mt<2;mt++)
        #pragma unroll
        for (int nt=0;nt<4;nt++)
            #pragma unroll
            for (int q=0;q<4;q++){
                int r = wm + mt*16 + g + ((q>=2)?8:0);
                int n = n0 + wn + nt*8 + 2*c + (q&1);
                if (isC){
                    float v = acc[mt][nt][q] + g_bcomb[n];
                    if (n < EE) g_hwh_h[(size_t)r*EE + n] = __float2half(v);
                    else        g_gate[(size_t)r*EE + (n-EE)] = sigfast(v);
                } else {
                    if (n < VSZ && g_dec[r] >= tt)
                        outp[(size_t)r*TCAP*VSZ + (size_t)tt*VSZ + n] = acc[mt][nt][q] + fc1b[n];
                }
            }
}

// ---------------- gstep: GRU GEMM + fused combine, split-K 8 ----------------
__global__ __launch_bounds__(256) void gstep(int t){
    __shared__ __align__(16) unsigned sb[8192];
    unsigned (*As)[64][17]  = (unsigned(*)[64][17])sb;
    unsigned (*Ws)[128][17] = (unsigned(*)[128][17])(sb + 2*64*17);
    int tile = blockIdx.x;              // 0..15
    int n0 = tile*128;
    float acc[2][4][4];
    #pragma unroll
    for (int i=0;i<2;i++)
        #pragma unroll
        for (int j=0;j<4;j++)
            #pragma unroll
            for (int q=0;q<4;q++) acc[i][j][q]=0.f;
    int kb = blockIdx.z * (KCAT/8);
    mm_body(g_inp, KCAT, g_Wg + (size_t)n0*KCAT, 128, KCAT, kb, kb + KCAT/8, As, Ws, acc);
    if (!splitk_reduce(acc, tile, 8)) return;

    int tid = threadIdx.x;
    int w = tid >> 5, lane = tid & 31, g = lane >> 2, c = lane & 3;
    int wm = (w >> 2) * 32, wn = (w & 3) * 32;
    float* Gt = (float*)sb;
    #pragma unroll
    for (int mt=0;mt<2;mt++)
        #pragma unroll
        for (int nt=0;nt<4;nt++)
            #pragma unroll
            for (int q=0;q<4;q++){
                int r  = wm + mt*16 + g + ((q>=2)?8:0);
                int cc = wn + nt*8 + 2*c + (q&1);
                Gt[r*128 + cc] = acc[mt][nt][q] + g_bg[n0 + cc];
            }
    __syncthreads();
    int jbase = n0 >> 2;
    for (int idx = tid; idx < 2048; idx += 256){
        int r  = idx >> 5;
        int jl = idx & 31;
        float G0 = Gt[r*128 + jl*4 + 0];
        float G1 = Gt[r*128 + jl*4 + 1];
        float G2 = Gt[r*128 + jl*4 + 2];
        float G3 = Gt[r*128 + jl*4 + 3];
        float rr = sigf(G0), zz = sigf(G1);
        float nn = tanhf(G2 + rr*G3);
        int j = jbase + jl;
        float h = g_h[r*HH + j];
        if (g_dec[r] >= t) g_h[r*HH + j] = (1.f - zz)*nn + zz*h;
    }
}

// ---------------- attention logits (high-occupancy: 4 p per block) ----------------
__global__ __launch_bounds__(256) void att_kernel(const float* __restrict__ Vw,
                                                  const float* __restrict__ Vb){
    int b = blockIdx.y, p0 = blockIdx.x*4;
    int tid = threadIdx.x;
    const uint4* xbase = (const uint4*)(g_xwx_h + (size_t)(b*PP + p0)*EE);
    uint4 hv = ((const uint4*)(g_hwh_h + (size_t)b*EE))[tid];
    float4 v0 = ((const float4*)Vw)[2*tid];
    float4 v1 = ((const float4*)Vw)[2*tid+1];
    float s[4];
    #pragma unroll
    for (int pp = 0; pp < 4; pp++){
        uint4 xv = xbase[(size_t)pp*(EE/8) + tid];
        unsigned t0 = tanh2(hadd2u(xv.x, hv.x));
        unsigned t1 = tanh2(hadd2u(xv.y, hv.y));
        unsigned t2 = tanh2(hadd2u(xv.z, hv.z));
        unsigned t3 = tanh2(hadd2u(xv.w, hv.w));
        float2 f0 = __half22float2(*(__half2*)&t0);
        float2 f1 = __half22float2(*(__half2*)&t1);
        float2 f2 = __half22float2(*(__half2*)&t2);
        float2 f3 = __half22float2(*(__half2*)&t3);
        float a = f0.x*v0.x + f0.y*v0.y;
        a = fmaf(f1.x, v0.z, a); a = fmaf(f1.y, v0.w, a);
        a = fmaf(f2.x, v1.x, a); a = fmaf(f2.y, v1.y, a);
        a = fmaf(f3.x, v1.z, a); a = fmaf(f3.y, v1.w, a);
        s[pp] = a;
    }
    #pragma unroll
    for (int pp = 0; pp < 4; pp++)
        #pragma unroll
        for (int o = 16; o > 0; o >>= 1) s[pp] += __shfl_xor_sync(0xffffffffu, s[pp], o);
    __shared__ float sh[4][8];
    if ((tid & 31) == 0)
        #pragma unroll
        for (int pp = 0; pp < 4; pp++) sh[pp][tid>>5] = s[pp];
    __syncthreads();
    if (tid < 4){
        float tt = 0.f;
        #pragma unroll
        for (int w2 = 0; w2 < 8; w2++) tt += sh[tid][w2];
        g_lam[b*PP + p0 + tid] = tt + Vb[0];
    }
}

// ---------------- zbuild: softmax + z (fp16 feats) + embed + h concat ----------------
__global__ __launch_bounds__(256) void zbuild_kernel(const int* __restrict__ caps,
                                                     const float* __restrict__ embw,
                                                     float* __restrict__ outp, int t){
    int b = blockIdx.y, tid = threadIdx.x, bx = blockIdx.x;
    if (bx >= 4){
        int tok = caps[b*TCAP + t];
        if (bx == 4){
            g_inp[(size_t)b*KCAT + 2048 + tid]       = embw[(size_t)tok*EMBD + tid];
            g_inp[(size_t)b*KCAT + 2048 + 256 + tid] = embw[(size_t)tok*EMBD + 256 + tid];
        } else {
            g_inp[(size_t)b*KCAT + 2560 + tid]       = g_h[b*HH + tid];
            g_inp[(size_t)b*KCAT + 2560 + 256 + tid] = g_h[b*HH + 256 + tid];
        }
        return;
    }
    __shared__ float red[256];
    __shared__ float salpha[PP];
    float v = (tid < PP) ? g_lam[b*PP + tid] : -1e30f;
    red[tid] = v; __syncthreads();
    for (int s2 = 128; s2 > 0; s2 >>= 1){ if (tid < s2) red[tid] = fmaxf(red[tid], red[tid+s2]); __syncthreads(); }
    float mx = red[0]; __syncthreads();
    float e = (tid < PP) ? expf(v - mx) : 0.f;
    red[tid] = e; __syncthreads();
    for (int s2 = 128; s2 > 0; s2 >>= 1){ if (tid < s2) red[tid] += red[tid+s2]; __syncthreads(); }
    float inv = 1.f / red[0];
    if (tid < PP) salpha[tid] = e * inv;
    __syncthreads();
    if (bx == 0 && tid < PP && g_dec[b] >= t)
        outp[ALPHA_OFF + (size_t)b*TCAP*PP + (size_t)t*PP + tid] = salpha[tid];

    int c2 = bx*256 + tid;              // half2 column index, 0..1023
    const __half2* fb = (const __half2*)(g_feat_h + (size_t)b*PP*EE) + c2;
    float2 acc = make_float2(0.f, 0.f);
    #pragma unroll 4
    for (int p = 0; p < PP; p++){
        float2 f2 = __half22float2(fb[(size_t)p*(EE/2)]);
        float al = salpha[p];
        acc.x = fmaf(al, f2.x, acc.x);
        acc.y = fmaf(al, f2.y, acc.y);
    }
    int e0 = 2*c2;
    g_inp[(size_t)b*KCAT + e0]     = g_gate[b*EE + e0]     * acc.x;
    g_inp[(size_t)b*KCAT + e0 + 1] = g_gate[b*EE + e0 + 1] * acc.y;
}

// ---------------- launch ----------------
extern "C" void kernel_launch(void* const* d_in, const int* in_sizes, int n_in,
                              void* d_out, int out_size){
    const float* features = (const float*)d_in[0];
    const int*   captions = (const int*)  d_in[1];
    const int*   lengths  = (const int*)  d_in[2];
    const float* Wx_w  = (const float*)d_in[3];
    const float* Wx_b  = (const float*)d_in[4];
    const float* Wh_w  = (const float*)d_in[5];
    const float* Wh_b  = (const float*)d_in[6];
    const float* V_w   = (const float*)d_in[7];
    const float* V_b   = (const float*)d_in[8];
    const float* ih_w  = (const float*)d_in[9];
    const float* ih_b  = (const float*)d_in[10];
    const float* fb_w  = (const float*)d_in[11];
    const float* fb_b  = (const float*)d_in[12];
    const float* emb_w = (const float*)d_in[13];
    const float* gih_w = (const float*)d_in[14];
    const float* gih_b = (const float*)d_in[15];
    const float* ghh_w = (const float*)d_in[16];
    const float* ghh_b = (const float*)d_in[17];
    const float* fc1_w = (const float*)d_in[18];
    const float* fc1_b = (const float*)d_in[19];
    float* out = (float*)d_out;

    cudaMemsetAsync(d_out, 0, (size_t)out_size * sizeof(float), 0);
    dec_kernel<<<1, 64>>>(lengths, out);
    mean_kernel<<<dim3(EE/256, BB), 256>>>(features);
    feat2h<<<(int)(((size_t)BPP*EE/2)/256), 256>>>(features);
    wx2h<<<(int)(((size_t)EE*EE/2)/256), 256>>>(Wx_w);
    build_wcomb<<<(4096*512)/256, 256>>>(Wh_w, Wh_b, fb_w, fb_b);
    build_wg<<<(int)(((size_t)2048*KCAT)/256), 256>>>(gih_w, gih_b, ghh_w, ghh_b);
    h0_kernel<<<4096, 256>>>(ih_w, ih_b);
    xwx_h16<<<dim3(EE/128, BPP/128), 256>>>(Wx_b);

    for (int t = 0; t < TMAXX; t++){
        wstep<<<dim3(111, 1, 4), 256>>>(fc1_w, fc1_b, out, t);   // hwh/gate(t) + fc1(t-1)
        att_kernel<<<dim3(PP/4, BB), 256>>>(V_w, V_b);
        zbuild_kernel<<<dim3(6, BB), 256>>>(captions, emb_w, out, t);
        gstep<<<dim3(16, 1, 8), 256>>>(t);                        // GRU GEMM + combine + h update
    }
    wstep<<<dim3(111, 1, 4), 256>>>(fc1_w, fc1_b, out, TMAXX);    // final fc1(48)
}

// round 17
// speedup vs baseline: 1.5522x; 1.0190x over previous
#include <cuda_runtime.h>
#include <cuda_fp16.h>
#include <math.h>

#define BB    64
#define PP    196
#define EE    2048
#define HH    512
#define EMBD  512
#define VSZ   10000
#define TCAP  50
#define TMAXX 49
#define BPP   (BB*PP)
#define KIH   (EE+EMBD)       // 2560
#define KCAT  3072            // EE+EMBD+HH

#define PRED_SZ   ((size_t)BB*TCAP*VSZ)
#define ALPHA_OFF PRED_SZ
#define ALPHA_SZ  ((size_t)BB*TCAP*PP)
#define DEC_OFF   (ALPHA_OFF + ALPHA_SZ)

// ---------------- scratch ----------------
__device__ __half g_xwx_h[(size_t)BPP*EE];     // fp16 attention projections
__device__ __half g_feat_h[(size_t)BPP*EE];    // fp16 features
__device__ __half g_Wxh[(size_t)EE*EE];        // fp16 Wx weight
__device__ __half g_hwh_h[BB*EE];
__device__ float g_fm  [BB*EE];
__device__ float g_h   [BB*HH];
__device__ float g_gate[BB*EE];
__device__ float g_lam [BB*PP];
__device__ float g_inp [BB*KCAT];
__device__ int   g_dec [BB];
__device__ float g_part[(size_t)111*16*8192];
__device__ unsigned g_cnt[128];                // zero-init; finisher resets
__device__ float g_Wcomb[4096*512];            // [Wh_w ; f_beta_w]
__device__ float g_bcomb[4096];
__device__ float g_Wg[(size_t)2048*KCAT];      // gate-interleaved GRU weight
__device__ float g_bg[2048];

// ---------------- helpers ----------------
__device__ __forceinline__ unsigned tf32c(float x){
    unsigned r; asm("cvt.rna.tf32.f32 %0, %1;" : "=r"(r) : "f"(x)); return r;
}
__device__ __forceinline__ void mma8(float* c, unsigned a0,unsigned a1,unsigned a2,unsigned a3,
                                     unsigned b0,unsigned b1){
    asm volatile("mma.sync.aligned.m16n8k8.row.col.f32.tf32.tf32.f32 "
        "{%0,%1,%2,%3}, {%4,%5,%6,%7}, {%8,%9}, {%0,%1,%2,%3};"
        : "+f"(c[0]),"+f"(c[1]),"+f"(c[2]),"+f"(c[3])
        : "r"(a0),"r"(a1),"r"(a2),"r"(a3),"r"(b0),"r"(b1));
}
__device__ __forceinline__ void mma16h(float* c, unsigned a0,unsigned a1,unsigned a2,unsigned a3,
                                       unsigned b0,unsigned b1){
    asm volatile("mma.sync.aligned.m16n8k16.row.col.f32.f16.f16.f32 "
        "{%0,%1,%2,%3}, {%4,%5,%6,%7}, {%8,%9}, {%0,%1,%2,%3};"
        : "+f"(c[0]),"+f"(c[1]),"+f"(c[2]),"+f"(c[3])
        : "r"(a0),"r"(a1),"r"(a2),"r"(a3),"r"(b0),"r"(b1));
}
__device__ __forceinline__ unsigned hadd2u(unsigned a, unsigned b){
    unsigned r; asm("add.f16x2 %0,%1,%2;" : "=r"(r) : "r"(a), "r"(b)); return r;
}
__device__ __forceinline__ unsigned tanh2(unsigned x){
    unsigned r; asm("tanh.approx.f16x2 %0,%1;" : "=r"(r) : "r"(x)); return r;
}
__device__ __forceinline__ void cpa16(void* smem, const void* g){
    unsigned sa = (unsigned)__cvta_generic_to_shared(smem);
    asm volatile("cp.async.cg.shared.global [%0], [%1], 16;" :: "r"(sa), "l"(g));
}
__device__ __forceinline__ void cpcommit(){ asm volatile("cp.async.commit_group;"); }
__device__ __forceinline__ void cpwait1(){ asm volatile("cp.async.wait_group 1;"); }
__device__ __forceinline__ float sigf(float x){ return 1.f/(1.f+expf(-x)); }
__device__ __forceinline__ float sigfast(float x){ return 1.f/(1.f+__expf(-x)); }

// ---------------- preamble ----------------
__global__ void dec_kernel(const int* __restrict__ lengths, float* __restrict__ outp){
    int b = threadIdx.x;
    if (b < BB){ int d = lengths[b]-1; g_dec[b] = d; outp[DEC_OFF+b] = (float)d; }
}

__global__ __launch_bounds__(256) void mean_kernel(const float* __restrict__ feat){
    int b = blockIdx.y;
    int e = blockIdx.x*256 + threadIdx.x;
    const float* f = feat + (size_t)b*PP*EE + e;
    float s = 0.f;
    #pragma unroll 4
    for (int p = 0; p < PP; p++) s += f[(size_t)p*EE];
    g_fm[b*EE+e] = s * (1.f/(float)PP);
}

// fp32->fp16 converters (16B transactions; device-symbol dst referenced inside kernel)
__global__ __launch_bounds__(256) void feat2h(const float* __restrict__ f){
    size_t i = (size_t)blockIdx.x*256 + threadIdx.x;   // over BPP*EE/4 float4
    float4 v = ((const float4*)f)[i];
    __half2 h0 = __floats2half2_rn(v.x, v.y);
    __half2 h1 = __floats2half2_rn(v.z, v.w);
    uint2 o; o.x = *(unsigned*)&h0; o.y = *(unsigned*)&h1;
    ((uint2*)g_feat_h)[i] = o;
}
__global__ __launch_bounds__(256) void wx2h(const float* __restrict__ w){
    size_t i = (size_t)blockIdx.x*256 + threadIdx.x;   // over EE*EE/4 float4
    float4 v = ((const float4*)w)[i];
    __half2 h0 = __floats2half2_rn(v.x, v.y);
    __half2 h1 = __floats2half2_rn(v.z, v.w);
    uint2 o; o.x = *(unsigned*)&h0; o.y = *(unsigned*)&h1;
    ((uint2*)g_Wxh)[i] = o;
}

__global__ __launch_bounds__(256) void build_wcomb(const float* __restrict__ Whw, const float* __restrict__ Whb,
                                                   const float* __restrict__ fbw, const float* __restrict__ fbb){
    int idx = blockIdx.x*256 + threadIdx.x;      // 4096*512
    int n = idx >> 9, k = idx & 511;
    g_Wcomb[idx] = (n < EE) ? Whw[n*HH+k] : fbw[(n-EE)*HH+k];
    if (k == 0) g_bcomb[n] = (n < EE) ? Whb[n] : fbb[n-EE];
}

// gate-interleaved GRU weight: new row m = j*4+q, q in {r,z,n,hn}
__global__ __launch_bounds__(256) void build_wg(const float* __restrict__ gihw, const float* __restrict__ gihb,
                                                const float* __restrict__ ghhw, const float* __restrict__ ghhb){
    size_t idx = (size_t)blockIdx.x*256 + threadIdx.x;    // 2048*3072
    int m = (int)(idx / KCAT), k = (int)(idx % KCAT);
    int j = m >> 2, q = m & 3;
    int n = q*512 + j;
    float v;
    if (n < 1024)       v = (k < KIH) ? gihw[(size_t)n*KIH+k] : ghhw[(size_t)n*HH + (k-KIH)];
    else if (n < 1536)  v = (k < KIH) ? gihw[(size_t)n*KIH+k] : 0.f;
    else                v = (k < KIH) ? 0.f : ghhw[(size_t)(n-512)*HH + (k-KIH)];
    g_Wg[idx] = v;
    if (k == 0){
        float bb;
        if (n < 1024)      bb = gihb[n] + ghhb[n];
        else if (n < 1536) bb = gihb[n];
        else               bb = ghhb[n-512];
        g_bg[m] = bb;
    }
}

__global__ __launch_bounds__(256) void h0_kernel(const float* __restrict__ W,
                                                 const float* __restrict__ bv){
    int gw = blockIdx.x*8 + (threadIdx.x >> 5);
    int lane = threadIdx.x & 31;
    int b = gw >> 9, n = gw & 511;
    const float* a = g_fm + (size_t)b*EE;
    const float* w = W + (size_t)n*EE;
    float s = 0.f;
    #pragma unroll 4
    for (int k = lane; k < EE; k += 32) s = fmaf(a[k], w[k], s);
    #pragma unroll
    for (int o = 16; o > 0; o >>= 1) s += __shfl_xor_sync(0xffffffffu, s, o);
    if (lane == 0) g_h[b*HH + n] = s + bv[n];
}

// ---------------- xwx: fp16 mma GEMM from device-global fp16 buffers ----------------
#define XPH 40
__global__ __launch_bounds__(256) void xwx_h16(const float* __restrict__ bias){
    __shared__ __half As[2][128*XPH];
    __shared__ __half Bs[2][128*XPH];
    int tid = threadIdx.x;
    int m0 = blockIdx.y*128, n0 = blockIdx.x*128;
    int rc = tid >> 1, kc = (tid & 1) * 16;
    const __half* Ap = g_feat_h + (size_t)(m0+rc)*EE + kc;
    const __half* Wp = g_Wxh   + (size_t)(n0+rc)*EE + kc;
    int wq = tid >> 5, lane = tid & 31, g = lane >> 2, ct = lane & 3;
    int wm = (wq >> 2) * 64, wn = (wq & 3) * 32;

    float acc[4][4][4];
    #pragma unroll
    for (int i=0;i<4;i++)
        #pragma unroll
        for (int j=0;j<4;j++)
            #pragma unroll
            for (int q=0;q<4;q++) acc[i][j][q] = 0.f;

    #pragma unroll
    for (int s = 0; s < 2; s++){
        int k0 = s*32;
        cpa16(&As[s][rc*XPH + kc],     Ap + k0);
        cpa16(&As[s][rc*XPH + kc + 8], Ap + k0 + 8);
        cpa16(&Bs[s][rc*XPH + kc],     Wp + k0);
        cpa16(&Bs[s][rc*XPH + kc + 8], Wp + k0 + 8);
        cpcommit();
    }

    for (int k0 = 0; k0 < EE; k0 += 32){
        int s = (k0 >> 5) & 1;
        cpwait1();
        __syncthreads();
        #pragma unroll
        for (int kq = 0; kq < 2; kq++){
            int k16 = kq*16;
            unsigned ah[4][4], bh[4][2];
            #pragma unroll
            for (int mt=0;mt<4;mt++){
                int rm = wm + mt*16;
                ah[mt][0] = *(const unsigned*)&As[s][(rm+g  )*XPH + k16 + 2*ct];
                ah[mt][1] = *(const unsigned*)&As[s][(rm+g+8)*XPH + k16 + 2*ct];
                ah[mt][2] = *(const unsigned*)&As[s][(rm+g  )*XPH + k16 + 2*ct + 8];
                ah[mt][3] = *(const unsigned*)&As[s][(rm+g+8)*XPH + k16 + 2*ct + 8];
            }
            #pragma unroll
            for (int nt=0;nt<4;nt++){
                int nb = wn + nt*8;
                bh[nt][0] = *(const unsigned*)&Bs[s][(nb+g)*XPH + k16 + 2*ct];
                bh[nt][1] = *(const unsigned*)&Bs[s][(nb+g)*XPH + k16 + 2*ct + 8];
            }
            #pragma unroll
            for (int mt=0;mt<4;mt++)
                #pragma unroll
                for (int nt=0;nt<4;nt++)
                    mma16h(acc[mt][nt], ah[mt][0],ah[mt][1],ah[mt][2],ah[mt][3], bh[nt][0],bh[nt][1]);
        }
        __syncthreads();
        {
            int kn = k0 + 64;
            if (kn < EE){
                cpa16(&As[s][rc*XPH + kc],     Ap + kn);
                cpa16(&As[s][rc*XPH + kc + 8], Ap + kn + 8);
                cpa16(&Bs[s][rc*XPH + kc],     Wp + kn);
                cpa16(&Bs[s][rc*XPH + kc + 8], Wp + kn + 8);
            }
            cpcommit();   // unconditional: pending-group count stays honest
        }
    }
    #pragma unroll
    for (int mt=0;mt<4;mt++)
        #pragma unroll
        for (int nt=0;nt<4;nt++){
            int cn = n0 + wn + nt*8 + 2*ct;
            float b0 = bias[cn], b1 = bias[cn+1];
            size_t r1 = (size_t)(m0 + wm + mt*16 + g);
            *(__half2*)&g_xwx_h[r1*EE + cn]     = __floats2half2_rn(acc[mt][nt][0]+b0, acc[mt][nt][1]+b1);
            *(__half2*)&g_xwx_h[(r1+8)*EE + cn] = __floats2half2_rn(acc[mt][nt][2]+b0, acc[mt][nt][3]+b1);
        }
}

// ---------------- shared 64x128 tf32 tile body; prec=1 adds 3-term compensation ----------------
__device__ __forceinline__ void mm_body(const float* __restrict__ A, int lda,
                                        const float* __restrict__ W0, int wrows, int K,
                                        int kbeg, int kend, int prec,
                                        unsigned (*As)[64][17], unsigned (*Ws)[128][17],
                                        float acc[2][4][4]){
    int tid = threadIdx.x;
    int arow = tid >> 2, acol = (tid & 3) * 4;
    int brow = tid >> 1, bcol = (tid & 1) * 8;
    bool bok = brow < wrows;
    const float* Ap = A + (size_t)arow*lda + acol;
    const float* Wp = W0 + (size_t)brow*K + bcol;
    int w = tid >> 5, lane = tid & 31, g = lane >> 2, c = lane & 3;
    int wm = (w >> 2) * 32, wn = (w & 3) * 32;
    float4 ra = *(const float4*)(Ap + kbeg);
    float4 rb0 = make_float4(0,0,0,0), rb1 = rb0;
    if (bok){ rb0 = *(const float4*)(Wp + kbeg); rb1 = *(const float4*)(Wp + kbeg + 4); }
    for (int k0 = kbeg; k0 < kend; k0 += 16){
        float av[4] = {ra.x,ra.y,ra.z,ra.w};
        #pragma unroll
        for (int j=0;j<4;j++){
            unsigned hi = tf32c(av[j]);
            As[0][arow][acol+j] = hi;
            if (prec) As[1][arow][acol+j] = tf32c(av[j] - __uint_as_float(hi));
        }
        float bvv[8] = {rb0.x,rb0.y,rb0.z,rb0.w, rb1.x,rb1.y,rb1.z,rb1.w};
        #pragma unroll
        for (int j=0;j<8;j++){
            unsigned hi = tf32c(bvv[j]);
            Ws[0][brow][bcol+j] = hi;
            if (prec) Ws[1][brow][bcol+j] = tf32c(bvv[j] - __uint_as_float(hi));
        }
        __syncthreads();
        if (k0 + 16 < kend){
            ra = *(const float4*)(Ap + k0 + 16);
            if (bok){ rb0 = *(const float4*)(Wp + k0 + 16); rb1 = *(const float4*)(Wp + k0 + 20); }
        }
        #pragma unroll
        for (int kq = 0; kq < 2; kq++){
            int k8 = kq*8;
            unsigned ah[2][4], bh[4][2];
            #pragma unroll
            for (int mt=0;mt<2;mt++){
                int rm = wm + mt*16;
                ah[mt][0]=As[0][rm+g][k8+c];   ah[mt][1]=As[0][rm+g+8][k8+c];
                ah[mt][2]=As[0][rm+g][k8+c+4]; ah[mt][3]=As[0][rm+g+8][k8+c+4];
            }
            #pragma unroll
            for (int nt=0;nt<4;nt++){
                int nb = wn + nt*8;
                bh[nt][0]=Ws[0][nb+g][k8+c]; bh[nt][1]=Ws[0][nb+g][k8+c+4];
            }
            #pragma unroll
            for (int mt=0;mt<2;mt++)
                #pragma unroll
                for (int nt=0;nt<4;nt++)
                    mma8(acc[mt][nt], ah[mt][0],ah[mt][1],ah[mt][2],ah[mt][3], bh[nt][0],bh[nt][1]);
            if (prec){
                unsigned al[2][4], bl[4][2];
                #pragma unroll
                for (int mt=0;mt<2;mt++){
                    int rm = wm + mt*16;
                    al[mt][0]=As[1][rm+g][k8+c];   al[mt][1]=As[1][rm+g+8][k8+c];
                    al[mt][2]=As[1][rm+g][k8+c+4]; al[mt][3]=As[1][rm+g+8][k8+c+4];
                }
                #pragma unroll
                for (int nt=0;nt<4;nt++){
                    int nb = wn + nt*8;
                    bl[nt][0]=Ws[1][nb+g][k8+c]; bl[nt][1]=Ws[1][nb+g][k8+c+4];
                }
                #pragma unroll
                for (int mt=0;mt<2;mt++)
                    #pragma unroll
                    for (int nt=0;nt<4;nt++){
                        mma8(acc[mt][nt], al[mt][0],al[mt][1],al[mt][2],al[mt][3], bh[nt][0],bh[nt][1]);
                        mma8(acc[mt][nt], ah[mt][0],ah[mt][1],ah[mt][2],ah[mt][3], bl[nt][0],bl[nt][1]);
                    }
            }
        }
        __syncthreads();
    }
}

// split-K partials laid out with stride 16 (max ksplit)
__device__ bool splitk_reduce(float acc[2][4][4], int slot, int ksplit){
    __shared__ unsigned s_last;
    int tid = threadIdx.x;
    int w = tid >> 5, lane = tid & 31, g = lane >> 2, c = lane & 3;
    int wm = (w >> 2) * 32, wn = (w & 3) * 32;
    float* pp = &g_part[((size_t)slot*16 + blockIdx.z)*8192];
    #pragma unroll
    for (int mt=0;mt<2;mt++)
        #pragma unroll
        for (int nt=0;nt<4;nt++){
            int r1 = wm + mt*16 + g;
            int cc = wn + nt*8 + 2*c;
            pp[r1*128 + cc]       = acc[mt][nt][0];
            pp[r1*128 + cc+1]     = acc[mt][nt][1];
            pp[(r1+8)*128 + cc]   = acc[mt][nt][2];
            pp[(r1+8)*128 + cc+1] = acc[mt][nt][3];
        }
    __threadfence();
    __syncthreads();
    if (tid == 0)
        s_last = (atomicAdd(&g_cnt[slot], 1u) == (unsigned)(ksplit-1)) ? 1u : 0u;
    __syncthreads();
    if (!s_last) return false;
    __threadfence();
    #pragma unroll
    for (int mt=0;mt<2;mt++)
        #pragma unroll
        for (int nt=0;nt<4;nt++){
            int r1 = wm + mt*16 + g;
            int cc = wn + nt*8 + 2*c;
            float s0=0.f,s1=0.f,s2=0.f,s3=0.f;
            for (int kz = 0; kz < ksplit; kz++){
                const float* q = &g_part[((size_t)slot*16 + kz)*8192];
                s0 += q[r1*128 + cc];     s1 += q[r1*128 + cc+1];
                s2 += q[(r1+8)*128 + cc]; s3 += q[(r1+8)*128 + cc+1];
            }
            acc[mt][nt][0]=s0; acc[mt][nt][1]=s1; acc[mt][nt][2]=s2; acc[mt][nt][3]=s3;
        }
    __syncthreads();
    if (tid == 0) g_cnt[slot] = 0;
    return true;
}

// ---------------- wstep: hwh/gate(t) + fc1(t-1), split-K 4, single tf32 ----------------
__global__ __launch_bounds__(256) void wstep(const float* __restrict__ fc1w,
                                             const float* __restrict__ fc1b,
                                             float* __restrict__ outp, int t){
    int tile = blockIdx.x;              // 0..110
    bool isC = tile < 32;
    if (isC  && t == TMAXX) return;
    if (!isC && t == 0)     return;
    __shared__ unsigned As[2][64][17];
    __shared__ unsigned Ws[2][128][17];
    int n0 = isC ? tile*128 : (tile-32)*128;
    const float* W = isC ? (g_Wcomb + (size_t)n0*HH) : (fc1w + (size_t)n0*HH);
    int wrows = isC ? 128 : (VSZ - n0 < 128 ? VSZ - n0 : 128);
    float acc[2][4][4];
    #pragma unroll
    for (int i=0;i<2;i++)
        #pragma unroll
        for (int j=0;j<4;j++)
            #pragma unroll
            for (int q=0;q<4;q++) acc[i][j][q]=0.f;
    int kb = blockIdx.z * (HH/4);
    mm_body(g_h, HH, W, wrows, HH, kb, kb + HH/4, 0, As, Ws, acc);
    if (!splitk_reduce(acc, tile, 4)) return;

    int tid = threadIdx.x;
    int w = tid >> 5, lane = tid & 31, g = lane >> 2, c = lane & 3;
    int wm = (w >> 2) * 32, wn = (w & 3) * 32;
    int tt = t - 1;
    #pragma unroll
    for (int mt=0;mt<2;mt++)
        #pragma unroll
        for (int nt=0;nt<4;nt++)
            #pragma unroll
            for (int q=0;q<4;q++){
                int r = wm + mt*16 + g + ((q>=2)?8:0);
                int n = n0 + wn + nt*8 + 2*c + (q&1);
                if (isC){
                    float v = acc[mt][nt][q] + g_bcomb[n];
                    if (n < EE) g_hwh_h[(size_t)r*EE + n] = __float2half(v);
                    else        g_gate[(size_t)r*EE + (n-EE)] = sigfast(v);
                } else {
                    if (n < VSZ && g_dec[r] >= tt)
                        outp[(size_t)r*TCAP*VSZ + (size_t)tt*VSZ + n] = acc[mt][nt][q] + fc1b[n];
                }
            }
}

// ---------------- gstep: GRU GEMM + fused combine, split-K 16, compensated ----------------
__global__ __launch_bounds__(256) void gstep(int t){
    __shared__ __align__(16) unsigned sb[8192];
    unsigned (*As)[64][17]  = (unsigned(*)[64][17])sb;
    unsigned (*Ws)[128][17] = (unsigned(*)[128][17])(sb + 2*64*17);
    int tile = blockIdx.x;              // 0..15
    int n0 = tile*128;
    float acc[2][4][4];
    #pragma unroll
    for (int i=0;i<2;i++)
        #pragma unroll
        for (int j=0;j<4;j++)
            #pragma unroll
            for (int q=0;q<4;q++) acc[i][j][q]=0.f;
    int kb = blockIdx.z * (KCAT/16);
    mm_body(g_inp, KCAT, g_Wg + (size_t)n0*KCAT, 128, KCAT, kb, kb + KCAT/16, 1, As, Ws, acc);
    if (!splitk_reduce(acc, tile, 16)) return;

    int tid = threadIdx.x;
    int w = tid >> 5, lane = tid & 31, g = lane >> 2, c = lane & 3;
    int wm = (w >> 2) * 32, wn = (w & 3) * 32;
    float* Gt = (float*)sb;
    #pragma unroll
    for (int mt=0;mt<2;mt++)
        #pragma unroll
        for (int nt=0;nt<4;nt++)
            #pragma unroll
            for (int q=0;q<4;q++){
                int r  = wm + mt*16 + g + ((q>=2)?8:0);
                int cc = wn + nt*8 + 2*c + (q&1);
                Gt[r*128 + cc] = acc[mt][nt][q] + g_bg[n0 + cc];
            }
    __syncthreads();
    int jbase = n0 >> 2;
    for (int idx = tid; idx < 2048; idx += 256){
        int r  = idx >> 5;
        int jl = idx & 31;
        float G0 = Gt[r*128 + jl*4 + 0];
        float G1 = Gt[r*128 + jl*4 + 1];
        float G2 = Gt[r*128 + jl*4 + 2];
        float G3 = Gt[r*128 + jl*4 + 3];
        float rr = sigf(G0), zz = sigf(G1);
        float nn = tanhf(G2 + rr*G3);
        int j = jbase + jl;
        float h = g_h[r*HH + j];
        if (g_dec[r] >= t) g_h[r*HH + j] = (1.f - zz)*nn + zz*h;
    }
}

// ---------------- attention logits (high-occupancy: 4 p per block) ----------------
__global__ __launch_bounds__(256) void att_kernel(const float* __restrict__ Vw,
                                                  const float* __restrict__ Vb){
    int b = blockIdx.y, p0 = blockIdx.x*4;
    int tid = threadIdx.x;
    const uint4* xbase = (const uint4*)(g_xwx_h + (size_t)(b*PP + p0)*EE);
    uint4 hv = ((const uint4*)(g_hwh_h + (size_t)b*EE))[tid];
    float4 v0 = ((const float4*)Vw)[2*tid];
    float4 v1 = ((const float4*)Vw)[2*tid+1];
    float s[4];
    #pragma unroll
    for (int pp = 0; pp < 4; pp++){
        uint4 xv = xbase[(size_t)pp*(EE/8) + tid];
        unsigned t0 = tanh2(hadd2u(xv.x, hv.x));
        unsigned t1 = tanh2(hadd2u(xv.y, hv.y));
        unsigned t2 = tanh2(hadd2u(xv.z, hv.z));
        unsigned t3 = tanh2(hadd2u(xv.w, hv.w));
        float2 f0 = __half22float2(*(__half2*)&t0);
        float2 f1 = __half22float2(*(__half2*)&t1);
        float2 f2 = __half22float2(*(__half2*)&t2);
        float2 f3 = __half22float2(*(__half2*)&t3);
        float a = f0.x*v0.x + f0.y*v0.y;
        a = fmaf(f1.x, v0.z, a); a = fmaf(f1.y, v0.w, a);
        a = fmaf(f2.x, v1.x, a); a = fmaf(f2.y, v1.y, a);
        a = fmaf(f3.x, v1.z, a); a = fmaf(f3.y, v1.w, a);
        s[pp] = a;
    }
    #pragma unroll
    for (int pp = 0; pp < 4; pp++)
        #pragma unroll
        for (int o = 16; o > 0; o >>= 1) s[pp] += __shfl_xor_sync(0xffffffffu, s[pp], o);
    __shared__ float sh[4][8];
    if ((tid & 31) == 0)
        #pragma unroll
        for (int pp = 0; pp < 4; pp++) sh[pp][tid>>5] = s[pp];
    __syncthreads();
    if (tid < 4){
        float tt = 0.f;
        #pragma unroll
        for (int w2 = 0; w2 < 8; w2++) tt += sh[tid][w2];
        g_lam[b*PP + p0 + tid] = tt + Vb[0];
    }
}

// ---------------- zbuild: softmax + z (fp16 feats) + embed + h concat ----------------
__global__ __launch_bounds__(256) void zbuild_kernel(const int* __restrict__ caps,
                                                     const float* __restrict__ embw,
                                                     float* __restrict__ outp, int t){
    int b = blockIdx.y, tid = threadIdx.x, bx = blockIdx.x;
    if (bx >= 4){
        int tok = caps[b*TCAP + t];
        if (bx == 4){
            g_inp[(size_t)b*KCAT + 2048 + tid]       = embw[(size_t)tok*EMBD + tid];
            g_inp[(size_t)b*KCAT + 2048 + 256 + tid] = embw[(size_t)tok*EMBD + 256 + tid];
        } else {
            g_inp[(size_t)b*KCAT + 2560 + tid]       = g_h[b*HH + tid];
            g_inp[(size_t)b*KCAT + 2560 + 256 + tid] = g_h[b*HH + 256 + tid];
        }
        return;
    }
    __shared__ float red[256];
    __shared__ float salpha[PP];
    float v = (tid < PP) ? g_lam[b*PP + tid] : -1e30f;
    red[tid] = v; __syncthreads();
    for (int s2 = 128; s2 > 0; s2 >>= 1){ if (tid < s2) red[tid] = fmaxf(red[tid], red[tid+s2]); __syncthreads(); }
    float mx = red[0]; __syncthreads();
    float e = (tid < PP) ? expf(v - mx) : 0.f;
    red[tid] = e; __syncthreads();
    for (int s2 = 128; s2 > 0; s2 >>= 1){ if (tid < s2) red[tid] += red[tid+s2]; __syncthreads(); }
    float inv = 1.f / red[0];
    if (tid < PP) salpha[tid] = e * inv;
    __syncthreads();
    if (bx == 0 && tid < PP && g_dec[b] >= t)
        outp[ALPHA_OFF + (size_t)b*TCAP*PP + (size_t)t*PP + tid] = salpha[tid];

    int c2 = bx*256 + tid;              // half2 column index, 0..1023
    const __half2* fb = (const __half2*)(g_feat_h + (size_t)b*PP*EE) + c2;
    float2 acc = make_float2(0.f, 0.f);
    #pragma unroll 4
    for (int p = 0; p < PP; p++){
        float2 f2 = __half22float2(fb[(size_t)p*(EE/2)]);
        float al = salpha[p];
        acc.x = fmaf(al, f2.x, acc.x);
        acc.y = fmaf(al, f2.y, acc.y);
    }
    int e0 = 2*c2;
    g_inp[(size_t)b*KCAT + e0]     = g_gate[b*EE + e0]     * acc.x;
    g_inp[(size_t)b*KCAT + e0 + 1] = g_gate[b*EE + e0 + 1] * acc.y;
}

// ---------------- launch ----------------
extern "C" void kernel_launch(void* const* d_in, const int* in_sizes, int n_in,
                              void* d_out, int out_size){
    const float* features = (const float*)d_in[0];
    const int*   captions = (const int*)  d_in[1];
    const int*   lengths  = (const int*)  d_in[2];
    const float* Wx_w  = (const float*)d_in[3];
    const float* Wx_b  = (const float*)d_in[4];
    const float* Wh_w  = (const float*)d_in[5];
    const float* Wh_b  = (const float*)d_in[6];
    const float* V_w   = (const float*)d_in[7];
    const float* V_b   = (const float*)d_in[8];
    const float* ih_w  = (const float*)d_in[9];
    const float* ih_b  = (const float*)d_in[10];
    const float* fb_w  = (const float*)d_in[11];
    const float* fb_b  = (const float*)d_in[12];
    const float* emb_w = (const float*)d_in[13];
    const float* gih_w = (const float*)d_in[14];
    const float* gih_b = (const float*)d_in[15];
    const float* ghh_w = (const float*)d_in[16];
    const float* ghh_b = (const float*)d_in[17];
    const float* fc1_w = (const float*)d_in[18];
    const float* fc1_b = (const float*)d_in[19];
    float* out = (float*)d_out;

    cudaMemsetAsync(d_out, 0, (size_t)out_size * sizeof(float), 0);
    dec_kernel<<<1, 64>>>(lengths, out);
    mean_kernel<<<dim3(EE/256, BB), 256>>>(features);
    feat2h<<<(int)(((size_t)BPP*EE/4)/256), 256>>>(features);
    wx2h<<<(int)(((size_t)EE*EE/4)/256), 256>>>(Wx_w);
    build_wcomb<<<(4096*512)/256, 256>>>(Wh_w, Wh_b, fb_w, fb_b);
    build_wg<<<(int)(((size_t)2048*KCAT)/256), 256>>>(gih_w, gih_b, ghh_w, ghh_b);
    h0_kernel<<<4096, 256>>>(ih_w, ih_b);
    xwx_h16<<<dim3(EE/128, BPP/128), 256>>>(Wx_b);

    for (int t = 0; t < TMAXX; t++){
        wstep<<<dim3(111, 1, 4), 256>>>(fc1_w, fc1_b, out, t);   // hwh/gate(t) + fc1(t-1)
        att_kernel<<<dim3(PP/4, BB), 256>>>(V_w, V_b);
        zbuild_kernel<<<dim3(6, BB), 256>>>(captions, emb_w, out, t);
        gstep<<<dim3(16, 1, 16), 256>>>(t);                       // GRU GEMM + combine + h update
    }
    wstep<<<dim3(111, 1, 4), 256>>>(fc1_w, fc1_b, out, TMAXX);    // final fc1(48)
}